// round 14
// baseline (speedup 1.0000x reference)
#include <cuda_runtime.h>
#include <cuda_fp16.h>
#include <math.h>
#include <limits.h>
#include <stdint.h>

#define B_    8
#define NINST 16384
#define D_    512
#define C_    2
#define G_    8
#define KNN   4
#define BUF_  1024
#define DA_   128
#define M_    (B_*NINST)     /* 131072 */
#define MG    2048
#define NG    64
#define NN    1032
#define NNP   1152           /* NN padded to 9*128 */

// ---------------- scratch (device globals; no allocation) ----------------
__device__ __half g_xh[(size_t)M_ * D_];
__device__ __half g_midh[(size_t)M_ * D_];
__device__ __half g_wh[D_ * D_];      // Wdr^T fp16  [n][k]
__device__ __half g_wvuh[256 * D_];   // packed [V|U] blocks fp16  [n][k]
__device__ __half g_wg1h[D_ * D_];    // Wg1^T fp16
__device__ __half g_wg1sh[D_ * D_];   // Wg1s^T fp16
__device__ __half g_hh[(size_t)NNP * D_];   // h fp16 (padded, zero-init)
__device__ __half g_m1h[(size_t)NNP * D_];  // m1 fp16 (padded, zero-init)
__device__ float g_apart[2 * M_];
__device__ float g_af[NG * D_];
__device__ float g_a2[NG];
__device__ float g_bag[B_ * D_];
__device__ float g_xc[NN * D_];
__device__ float g_x2[NN * 256];
__device__ float g_sim[NN * NN];
__device__ int   g_idx[NN * KNN];
__device__ float g_h[NN * D_];
__device__ float g_h1[NN * D_];

// ---------------- helpers ----------------
#define SWZ(o) ((o) ^ (((o) >> 3) & 0x70))

static __device__ __forceinline__ uint32_t smem_u32(const void* p) {
    uint32_t a;
    asm("{ .reg .u64 t; cvta.to.shared.u64 t, %1; cvt.u32.u64 %0, t; }" : "=r"(a) : "l"(p));
    return a;
}

#define CP_ASYNC16(dst, src) \
    asm volatile("cp.async.cg.shared.global [%0], [%1], 16;" :: "r"(dst), "l"(src))
#define CP_COMMIT asm volatile("cp.async.commit_group;" ::: "memory")
#define CP_WAIT2  asm volatile("cp.async.wait_group 2;" ::: "memory")
#define CP_WAIT1  asm volatile("cp.async.wait_group 1;" ::: "memory")
#define CP_WAIT0  asm volatile("cp.async.wait_group 0;" ::: "memory")

static __device__ __forceinline__ void ldsm4(uint32_t& r0, uint32_t& r1,
                                             uint32_t& r2, uint32_t& r3, uint32_t addr) {
    asm volatile("ldmatrix.sync.aligned.m8n8.x4.shared.b16 {%0,%1,%2,%3}, [%4];"
                 : "=r"(r0), "=r"(r1), "=r"(r2), "=r"(r3) : "r"(addr));
}
static __device__ __forceinline__ void mma16816(float* d, const uint32_t* a, const uint32_t* b) {
    asm volatile("mma.sync.aligned.m16n8k16.row.col.f32.f16.f16.f32 "
                 "{%0,%1,%2,%3}, {%4,%5,%6,%7}, {%8,%9}, {%0,%1,%2,%3};"
                 : "+f"(d[0]), "+f"(d[1]), "+f"(d[2]), "+f"(d[3])
                 : "r"(a[0]), "r"(a[1]), "r"(a[2]), "r"(a[3]), "r"(b[0]), "r"(b[1]));
}

static __device__ __forceinline__ uint32_t pack_h2(float a, float b) {
    __half h0 = __float2half_rn(a), h1 = __float2half_rn(b);
    return (uint32_t)__half_as_ushort(h0) | ((uint32_t)__half_as_ushort(h1) << 16);
}

// fast transcendentals: MUFU ex2 + rcp.approx
static __device__ __forceinline__ float ftanh(float x) {
    float xc = fminf(fmaxf(x, -15.f), 15.f);
    float t = __expf(2.f * xc);
    return __fdividef(t - 1.f, t + 1.f);
}
static __device__ __forceinline__ float fsigm(float x) {
    return __fdividef(1.f, 1.f + __expf(-x));
}

// ---------------- prep: x -> fp16, grid-stride ----------------
__global__ void prepX(const float4* __restrict__ x4)
{
    size_t idx = (size_t)blockIdx.x * 256 + threadIdx.x;
    const size_t stride = (size_t)4096 * 256;
#pragma unroll
    for (int s = 0; s < 16; s++) {
        size_t i = idx + (size_t)s * stride;
        float4 v = x4[i];
        uint2 hw;
        hw.x = pack_h2(v.x, v.y);
        hw.y = pack_h2(v.z, v.w);
        *(uint2*)(g_xh + i * 4) = hw;
    }
}

// merged weight prep: 0..511 Wdr^T | 512..767 Wvu | 768..1279 Wg1^T | 1280..1791 Wg1s^T
__global__ void prepW(const float* __restrict__ W,
                      const float* __restrict__ Wv, const float* __restrict__ Wu,
                      const float* __restrict__ Wg1, const float* __restrict__ Wg1s)
{
    int bx = blockIdx.x, k = threadIdx.x;
    if (bx < 512) {
        g_wh[(size_t)bx * 512 + k] = __float2half_rn(W[(size_t)k * 512 + bx]);
    } else if (bx < 768) {
        int n = bx - 512;
        int blk = n >> 7, j = n & 127;
        int gc = blk * 64 + (j & 63);
        float w = (j < 64) ? Wv[(size_t)k * 128 + gc] : Wu[(size_t)k * 128 + gc];
        g_wvuh[(size_t)n * 512 + k] = __float2half_rn(w);
    } else if (bx < 1280) {
        int n = bx - 768;
        g_wg1h[(size_t)n * 512 + k] = __float2half_rn(Wg1[(size_t)k * 512 + n]);
    } else {
        int n = bx - 1280;
        g_wg1sh[(size_t)n * 512 + k] = __float2half_rn(Wg1s[(size_t)k * 512 + n]);
    }
}

// ---------------- mma.sync GEMM: 128x128 CTA tile, 3-stage ----------------
// MODE 0: kA — mid = relu(x@Wdr+b) -> g_midh (fp16);           K=512,  grid (4,1024)
// MODE 1: kB — fused gated-attention partial score -> g_apart;  K=512,  grid (2,1024)
// MODE 2: kG — h1 = relu(m1h@Wg1 + hh@Wg1s + bg1) -> g_h1;     K=2*512, grid (4,9), M guarded
#define GEMM_SMEM 98816   /* 3 x 32KB stage buffers (+pad) */
template<int MODE>
__global__ void __launch_bounds__(256, 2) gemm_mma(const float* __restrict__ p0,
                                                   const float* __restrict__ p1,
                                                   const float* __restrict__ p2)
{
    extern __shared__ char smem[];
    const uint32_t sb = smem_u32(smem);
    const int tid = threadIdx.x;
    const int lane = tid & 31, warp = tid >> 5;
    const int wm = warp >> 1, wn = warp & 1;
    const int bm = blockIdx.y * 128;
    const int bn = blockIdx.x * 128;
    constexpr int NIT = (MODE == 2) ? 16 : 8;

    float d[2][8][4];
#pragma unroll
    for (int mi = 0; mi < 2; mi++)
#pragma unroll
        for (int n = 0; n < 8; n++)
#pragma unroll
            for (int j = 0; j < 4; j++) d[mi][n][j] = 0.f;

    auto issue = [&](int i) {
        const int seg = i >> 3, kc = i & 7, buf = i % 3;
        const __half* Aseg = (MODE == 0) ? g_xh
                           : (MODE == 1) ? g_midh
                           : (seg ? g_hh : g_m1h);
        const __half* Bseg = (MODE == 0) ? g_wh
                           : (MODE == 1) ? g_wvuh
                           : (seg ? g_wg1sh : g_wg1h);
        const uint32_t abase = sb + buf * 32768;
        const uint32_t bbase = abase + 16384;
        const int k0 = kc * 64;
#pragma unroll
        for (int p = 0; p < 4; p++) {
            int idx = tid + p * 256;
            int r = idx >> 3, c = idx & 7;
            CP_ASYNC16(abase + SWZ(r * 128 + c * 16),
                       Aseg + (size_t)(bm + r) * 512 + k0 + c * 8);
            CP_ASYNC16(bbase + SWZ(r * 128 + c * 16),
                       Bseg + (size_t)(bn + r) * 512 + k0 + c * 8);
        }
        CP_COMMIT;
    };

    issue(0); issue(1);
    for (int i = 0; i < NIT; i++) {
        if (i + 2 < NIT)      { issue(i + 2); CP_WAIT2; }
        else if (i + 1 < NIT) { CP_WAIT1; }
        else                  { CP_WAIT0; }
        __syncthreads();
        const uint32_t abase = sb + (i % 3) * 32768;
        const uint32_t bbase = abase + 16384;
        const int lr = lane & 7, quad = lane >> 3;
#pragma unroll
        for (int ks = 0; ks < 4; ks++) {
            const int k0 = ks * 16;
            uint32_t afr[2][4];
#pragma unroll
            for (int mi = 0; mi < 2; mi++) {
                int row = wm * 32 + mi * 16 + (quad & 1) * 8 + lr;
                int col = k0 + (quad >> 1) * 8;
                ldsm4(afr[mi][0], afr[mi][1], afr[mi][2], afr[mi][3],
                      abase + SWZ(row * 128 + col * 2));
            }
            uint32_t bfr[4][4];
#pragma unroll
            for (int nj = 0; nj < 4; nj++) {
                int row = wn * 64 + nj * 16 + (quad >> 1) * 8 + lr;
                int col = k0 + (quad & 1) * 8;
                ldsm4(bfr[nj][0], bfr[nj][1], bfr[nj][2], bfr[nj][3],
                      bbase + SWZ(row * 128 + col * 2));
            }
#pragma unroll
            for (int mi = 0; mi < 2; mi++)
#pragma unroll
                for (int n = 0; n < 8; n++)
                    mma16816(d[mi][n], afr[mi], &bfr[n >> 1][(n & 1) * 2]);
        }
        __syncthreads();
    }

    if (MODE == 1) {
        float* tile = (float*)smem;          // [128][132]
        float* sbv = (float*)(smem + 67584);
        float* sbu = sbv + 64;
        float* sww = sbu + 64;
        if (tid < 64) {
            int gc = blockIdx.x * 64 + tid;
            sbv[tid] = p0[gc]; sbu[tid] = p1[gc]; sww[tid] = p2[gc];
        }
#pragma unroll
        for (int mi = 0; mi < 2; mi++)
#pragma unroll
            for (int n = 0; n < 8; n++) {
                int r = wm * 32 + mi * 16 + (lane >> 2);
                int col = wn * 64 + n * 8 + (lane & 3) * 2;
                tile[r * 132 + col]           = d[mi][n][0];
                tile[r * 132 + col + 1]       = d[mi][n][1];
                tile[(r + 8) * 132 + col]     = d[mi][n][2];
                tile[(r + 8) * 132 + col + 1] = d[mi][n][3];
            }
        __syncthreads();
        int r = tid >> 1, half = tid & 1;
        float s = 0.f;
#pragma unroll
        for (int q = 0; q < 32; q++) {
            int j = half * 32 + q;
            float V = ftanh(tile[r * 132 + j] + sbv[j]);
            float U = fsigm(tile[r * 132 + 64 + j] + sbu[j]);
            s += V * U * sww[j];
        }
        s += __shfl_xor_sync(0xFFFFFFFFu, s, 1);
        if (half == 0) g_apart[(size_t)blockIdx.x * M_ + bm + r] = s;
        return;
    }

    // -------- MODE 0 / MODE 2 epilogue: bias + relu --------
    float* tile = (float*)smem;          // [128][136]
    float* sbias = (float*)(smem + 69632);
    if (tid < 128) sbias[tid] = p0[bn + tid];
#pragma unroll
    for (int mi = 0; mi < 2; mi++)
#pragma unroll
        for (int n = 0; n < 8; n++) {
            int r = wm * 32 + mi * 16 + (lane >> 2);
            int col = wn * 64 + n * 8 + (lane & 3) * 2;
            tile[r * 136 + col]           = d[mi][n][0];
            tile[r * 136 + col + 1]       = d[mi][n][1];
            tile[(r + 8) * 136 + col]     = d[mi][n][2];
            tile[(r + 8) * 136 + col + 1] = d[mi][n][3];
        }
    __syncthreads();
#pragma unroll
    for (int q = 0; q < 16; q++) {
        int idx = q * 256 + tid;
        int r = idx >> 5, c4 = (idx & 31) * 4;
        float4 v = *(const float4*)(tile + r * 136 + c4);
        v.x = fmaxf(v.x + sbias[c4 + 0], 0.f);
        v.y = fmaxf(v.y + sbias[c4 + 1], 0.f);
        v.z = fmaxf(v.z + sbias[c4 + 2], 0.f);
        v.w = fmaxf(v.w + sbias[c4 + 3], 0.f);
        if (MODE == 0) {
            uint2 hw;
            hw.x = pack_h2(v.x, v.y);
            hw.y = pack_h2(v.z, v.w);
            size_t off = (size_t)(bm + r) * 512 + bn + c4;
            *(uint2*)(g_midh + off) = hw;
        } else {
            int row = bm + r;
            if (row < NN)
                *(float4*)(g_h1 + (size_t)row * 512 + bn + c4) = v;
        }
    }
}

// ---------------- kCaf: inline softmax + af accumulation ----------------
__global__ __launch_bounds__(256) void kCaf(const float* __restrict__ bw)
{
    const int bg = blockIdx.y;
    const int cx = blockIdx.x;
    const int tid = threadIdx.x;
    const int lane = tid & 31, wi = tid >> 5;
    __shared__ float sw[MG];
    __shared__ float red[256];
    __shared__ float sred[8][64];
    const float bw0 = bw[0];

    float mx = -1e30f;
    for (int m = tid; m < MG; m += 256) {
        size_t row = (size_t)bg * MG + m;
        float a = g_apart[row] + g_apart[M_ + row] + bw0;
        sw[m] = a;
        mx = fmaxf(mx, a);
    }
    red[tid] = mx; __syncthreads();
    for (int s = 128; s > 0; s >>= 1) {
        if (tid < s) red[tid] = fmaxf(red[tid], red[tid + s]);
        __syncthreads();
    }
    mx = red[0]; __syncthreads();
    float sum = 0.f;
    for (int m = tid; m < MG; m += 256) {
        float e = __expf(sw[m] - mx);
        sw[m] = e; sum += e;
    }
    red[tid] = sum; __syncthreads();
    for (int s = 128; s > 0; s >>= 1) {
        if (tid < s) red[tid] += red[tid + s];
        __syncthreads();
    }
    const float inv = __fdividef(1.f, red[0]);
    __syncthreads();

    const int c0 = cx * 64 + lane * 2;
    const __half* mh = g_midh + (size_t)bg * MG * 512 + c0;
    float acc0 = 0.f, acc1 = 0.f;
    int mbase = wi * 256;
#pragma unroll 4
    for (int m = 0; m < 256; m++) {
        size_t off = (size_t)(mbase + m) * 512;
        __half2 hv = *(const __half2*)(mh + off);
        float wm = sw[mbase + m];
        acc0 += wm * __low2float(hv);
        acc1 += wm * __high2float(hv);
    }
    sred[wi][lane * 2] = acc0;
    sred[wi][lane * 2 + 1] = acc1;
    __syncthreads();
    if (tid < 64) {
        float s = 0.f;
#pragma unroll
        for (int w2 = 0; w2 < 8; w2++) s += sred[w2][tid];
        g_af[bg * 512 + cx * 64 + tid] = s * inv;
    }
}

// ---------------- dispatcher: kDsub (0-63) | kD1 (64-127) | copyReh (128-1151) ----------------
__global__ __launch_bounds__(256) void kSmall(
    const float* __restrict__ Wsc, const float* __restrict__ bsc, float* __restrict__ out,
    const float* __restrict__ Wv2, const float* __restrict__ bv2,
    const float* __restrict__ Wu2, const float* __restrict__ bu2,
    const float* __restrict__ Ww2, const float* __restrict__ bw2,
    const float* __restrict__ reh)
{
    __shared__ float sbuf[640];
    const int bx = blockIdx.x, tid = threadIdx.x;
    if (bx < 64) {
        int i = bx;
        int c = tid >> 7, dt = tid & 127;
        float s = 0.f;
        for (int d = dt; d < 512; d += 128) s += g_af[i * 512 + d] * Wsc[d * 2 + c];
#pragma unroll
        for (int o = 16; o; o >>= 1) s += __shfl_xor_sync(0xFFFFFFFFu, s, o);
        if ((tid & 31) == 0) sbuf[tid >> 5] = s;
        __syncthreads();
        if (tid == 0 || tid == 128) {
            int base = c * 4;
            float acc = sbuf[base] + sbuf[base + 1] + sbuf[base + 2] + sbuf[base + 3];
            int b = i >> 3, g = i & 7;
            out[16 + (g * 8 + b) * 2 + c] = acc + bsc[c];
        }
    } else if (bx < 128) {
        int i = bx - 64;
        float* s_af = sbuf;
        float* red  = sbuf + 512;
        for (int k = tid; k < 512; k += 256) s_af[k] = g_af[i * 512 + k];
        __syncthreads();
        int c = tid;
        if (c < 128) {
            float v = 0.f, u = 0.f;
            for (int k = 0; k < 512; k++) {
                float xv = s_af[k];
                v += xv * Wv2[k * 128 + c];
                u += xv * Wu2[k * 128 + c];
            }
            red[c] = ftanh(v + bv2[c]) * fsigm(u + bu2[c]) * Ww2[c];
        }
        __syncthreads();
        for (int s = 64; s > 0; s >>= 1) {
            if (c < s) red[c] += red[c + s];
            __syncthreads();
        }
        if (c == 0) g_a2[i] = red[0] + bw2[0];
    } else {
        int r = bx - 128;
        for (int d = tid; d < 512; d += 256)
            g_xc[(size_t)(8 + r) * 512 + d] = reh[(size_t)r * 512 + d];
    }
}

// ---------------- kD2b: bag_feat + x_concat rows 0..7 + bag_pred ----------------
__global__ void kD2b(const float* __restrict__ Wbc, const float* __restrict__ bbc,
                     float* __restrict__ out)
{
    int b = blockIdx.x;
    int t = threadIdx.x;
    __shared__ float w[8];
    __shared__ float red0[16], red1[16];
    if (t == 0) {
        float mx = -1e30f;
        for (int g = 0; g < 8; g++) mx = fmaxf(mx, g_a2[b * 8 + g]);
        float s = 0.f; float e[8];
        for (int g = 0; g < 8; g++) { e[g] = __expf(g_a2[b * 8 + g] - mx); s += e[g]; }
        float inv = __fdividef(1.f, s);
        for (int g = 0; g < 8; g++) w[g] = e[g] * inv;
    }
    __syncthreads();
    float acc = 0.f;
    for (int g = 0; g < 8; g++) acc += w[g] * g_af[(b * 8 + g) * 512 + t];
    g_bag[b * 512 + t] = acc;
    g_xc[b * 512 + t] = acc;
    float s0 = acc * Wbc[t * 2 + 0];
    float s1 = acc * Wbc[t * 2 + 1];
#pragma unroll
    for (int o = 16; o; o >>= 1) {
        s0 += __shfl_xor_sync(0xFFFFFFFFu, s0, o);
        s1 += __shfl_xor_sync(0xFFFFFFFFu, s1, o);
    }
    if ((t & 31) == 0) { red0[t >> 5] = s0; red1[t >> 5] = s1; }
    __syncthreads();
    if (t == 0) {
        float a0 = 0.f, a1 = 0.f;
#pragma unroll
        for (int q = 0; q < 16; q++) { a0 += red0[q]; a1 += red1[q]; }
        out[b * 2 + 0] = a0 + bbc[0];
        out[b * 2 + 1] = a1 + bbc[1];
    }
}

// ---------------- gemmF2: x2 = normalize(leaky_relu(xc @ Wf + bf)); 64 rows x full 256 cols per CTA ----------------
__global__ __launch_bounds__(256) void gemmF2(const float* __restrict__ Bm,
                                              const float* __restrict__ bias)
{
    __shared__ float As[16][64];
    __shared__ float Bs[16][256];
    const int tid = threadIdx.x;
    const int bm = blockIdx.x * 64;
    const int lar = tid >> 2, lak = (tid & 3) * 4;
    const int tr = tid >> 4, tc = tid & 15;
    float acc[4][16];
#pragma unroll
    for (int i = 0; i < 4; i++)
#pragma unroll
        for (int j = 0; j < 16; j++) acc[i][j] = 0.f;

    for (int k0 = 0; k0 < 512; k0 += 16) {
        float4 av = make_float4(0.f, 0.f, 0.f, 0.f);
        if (bm + lar < NN) av = *(const float4*)(g_xc + (size_t)(bm + lar) * 512 + k0 + lak);
        As[lak + 0][lar] = av.x; As[lak + 1][lar] = av.y;
        As[lak + 2][lar] = av.z; As[lak + 3][lar] = av.w;
#pragma unroll
        for (int p = 0; p < 4; p++) {
            int idx = tid + p * 256;
            int r = idx >> 6, c = (idx & 63) * 4;
            *(float4*)&Bs[r][c] = *(const float4*)(Bm + (size_t)(k0 + r) * 256 + c);
        }
        __syncthreads();
#pragma unroll
        for (int k = 0; k < 16; k++) {
            float4 a = *(const float4*)&As[k][tr * 4];
            float ar[4] = {a.x, a.y, a.z, a.w};
            float br[16];
#pragma unroll
            for (int q = 0; q < 4; q++) {
                float4 b = *(const float4*)&Bs[k][tc * 16 + q * 4];
                br[q * 4] = b.x; br[q * 4 + 1] = b.y; br[q * 4 + 2] = b.z; br[q * 4 + 3] = b.w;
            }
#pragma unroll
            for (int i = 0; i < 4; i++)
#pragma unroll
                for (int j = 0; j < 16; j++) acc[i][j] += ar[i] * br[j];
        }
        __syncthreads();
    }
    // leaky + row-normalize: the 16 threads sharing tr are lanes (tr*16..tr*16+15) -> contiguous half-warp
#pragma unroll
    for (int i = 0; i < 4; i++) {
        float ss = 0.f;
#pragma unroll
        for (int j = 0; j < 16; j++) {
            float v = acc[i][j] + bias[tc * 16 + j];
            v = (v >= 0.f) ? v : 0.01f * v;
            acc[i][j] = v;
            ss += v * v;
        }
#pragma unroll
        for (int o = 1; o < 16; o <<= 1) ss += __shfl_xor_sync(0xFFFFFFFFu, ss, o, 16);
        float inv = __fdividef(1.f, sqrtf(ss) + 1e-12f);
        int row = bm + tr * 4 + i;
        if (row < NN) {
            float4 o0 = make_float4(acc[i][0] * inv, acc[i][1] * inv, acc[i][2] * inv, acc[i][3] * inv);
            float4 o1 = make_float4(acc[i][4] * inv, acc[i][5] * inv, acc[i][6] * inv, acc[i][7] * inv);
            float4 o2 = make_float4(acc[i][8] * inv, acc[i][9] * inv, acc[i][10] * inv, acc[i][11] * inv);
            float4 o3 = make_float4(acc[i][12] * inv, acc[i][13] * inv, acc[i][14] * inv, acc[i][15] * inv);
            float* dst = g_x2 + (size_t)row * 256 + tc * 16;
            *(float4*)(dst)      = o0;
            *(float4*)(dst + 4)  = o1;
            *(float4*)(dst + 8)  = o2;
            *(float4*)(dst + 12) = o3;
        }
    }
}

// ---------------- sim = xn @ xn^T (NT), guarded 64x64
__global__ __launch_bounds__(256) void ksim()
{
    __shared__ float As[16][64];
    __shared__ float Bs[16][64];
    const int tid = threadIdx.x;
    const int bm = blockIdx.y * 64, bn = blockIdx.x * 64;
    const int lar = tid >> 2, lak = (tid & 3) * 4;
    const int tr = tid >> 4, tc = tid & 15;
    float acc[4][4];
#pragma unroll
    for (int i = 0; i < 4; i++)
#pragma unroll
        for (int j = 0; j < 4; j++) acc[i][j] = 0.f;

    for (int k0 = 0; k0 < 256; k0 += 16) {
        float4 av = make_float4(0.f, 0.f, 0.f, 0.f);
        float4 bv = make_float4(0.f, 0.f, 0.f, 0.f);
        if (bm + lar < NN) av = *(const float4*)(g_x2 + (size_t)(bm + lar) * 256 + k0 + lak);
        if (bn + lar < NN) bv = *(const float4*)(g_x2 + (size_t)(bn + lar) * 256 + k0 + lak);
        As[lak + 0][lar] = av.x; As[lak + 1][lar] = av.y;
        As[lak + 2][lar] = av.z; As[lak + 3][lar] = av.w;
        Bs[lak + 0][lar] = bv.x; Bs[lak + 1][lar] = bv.y;
        Bs[lak + 2][lar] = bv.z; Bs[lak + 3][lar] = bv.w;
        __syncthreads();
#pragma unroll
        for (int k = 0; k < 16; k++) {
            float4 a = *(const float4*)&As[k][tr * 4];
            float4 b = *(const float4*)&Bs[k][tc * 4];
            float ar[4] = {a.x, a.y, a.z, a.w};
            float br[4] = {b.x, b.y, b.z, b.w};
#pragma unroll
            for (int i = 0; i < 4; i++)
#pragma unroll
                for (int j = 0; j < 4; j++) acc[i][j] += ar[i] * br[j];
        }
        __syncthreads();
    }
#pragma unroll
    for (int i = 0; i < 4; i++) {
        int row = bm + tr * 4 + i;
#pragma unroll
        for (int j = 0; j < 4; j++) {
            int col = bn + tc * 4 + j;
            if (row < NN && col < NN)
                g_sim[(size_t)row * NN + col] = acc[i][j];
        }
    }
}

// ---------------- top-4 (jax tie-break) fused with h = pad + mean(xc[idx]) ----------------
__device__ __forceinline__ void top4_insert(float* v, int* ix, float val, int id)
{
    for (int k = 0; k < 4; k++) {
        if (val > v[k] || (val == v[k] && id < ix[k])) {
            for (int q = 3; q > k; q--) { v[q] = v[q - 1]; ix[q] = ix[q - 1]; }
            v[k] = val; ix[k] = id;
            return;
        }
    }
}

__global__ void ktop4()
{
    int row = blockIdx.x, tid = threadIdx.x;
    const float* s = g_sim + (size_t)row * NN;
    float v[4] = {-1e30f, -1e30f, -1e30f, -1e30f};
    int ix[4] = {INT_MAX, INT_MAX, INT_MAX, INT_MAX};
    for (int c = tid; c < NN; c += 256) top4_insert(v, ix, s[c], c);
    __shared__ float sv[256][4];
    __shared__ int si[256][4];
#pragma unroll
    for (int k = 0; k < 4; k++) { sv[tid][k] = v[k]; si[tid][k] = ix[k]; }
    __syncthreads();
    for (int stride = 128; stride > 0; stride >>= 1) {
        if (tid < stride) {
#pragma unroll
            for (int k = 0; k < 4; k++)
                top4_insert(sv[tid], si[tid], sv[tid + stride][k], si[tid + stride][k]);
        }
        __syncthreads();
    }
    if (tid < 4) g_idx[row * 4 + tid] = si[0][tid];
    __syncthreads();
    int i0 = si[0][0], i1 = si[0][1], i2 = si[0][2], i3 = si[0][3];
    for (int d = tid; d < 512; d += 256) {
        float e = 0.25f * (g_xc[(size_t)i0 * 512 + d] + g_xc[(size_t)i1 * 512 + d] +
                           g_xc[(size_t)i2 * 512 + d] + g_xc[(size_t)i3 * 512 + d]);
        float p = (row < 8) ? g_bag[row * 512 + d] : 0.f;
        float hv = p + e;
        g_h[(size_t)row * 512 + d] = hv;
        g_hh[(size_t)row * 512 + d] = __float2half_rn(hv);
    }
}

// ---------------- kE5: m1h = fp16(mean(h[idx])) ----------------
__global__ void kE5()
{
    int i = blockIdx.x, tid = threadIdx.x;
    int i0 = g_idx[i * 4 + 0], i1 = g_idx[i * 4 + 1];
    int i2 = g_idx[i * 4 + 2], i3 = g_idx[i * 4 + 3];
    for (int d = tid; d < 512; d += 256) {
        float m1 = 0.25f *
            (g_h[(size_t)i0 * 512 + d] + g_h[(size_t)i1 * 512 + d] +
             g_h[(size_t)i2 * 512 + d] + g_h[(size_t)i3 * 512 + d]);
        g_m1h[(size_t)i * 512 + d] = __float2half_rn(m1);
    }
}

// ---------------- logits rows 0..7 -> out[144..159]; grid 8, block 256
__global__ void kE7(const float* __restrict__ Wg2, const float* __restrict__ Wg2s,
                    const float* __restrict__ bg2, float* __restrict__ out)
{
    int i = blockIdx.x, tid = threadIdx.x;
    int c = tid >> 7, dt = tid & 127;
    int i0 = g_idx[i * 4 + 0], i1 = g_idx[i * 4 + 1];
    int i2 = g_idx[i * 4 + 2], i3 = g_idx[i * 4 + 3];
    float s = 0.f;
    for (int d = dt; d < 512; d += 128) {
        float m2 = 0.25f * (g_h1[(size_t)i0 * 512 + d] + g_h1[(size_t)i1 * 512 + d] +
                            g_h1[(size_t)i2 * 512 + d] + g_h1[(size_t)i3 * 512 + d]);
        s += m2 * Wg2[d * 2 + c] + g_h1[(size_t)i * 512 + d] * Wg2s[d * 2 + c];
    }
#pragma unroll
    for (int o = 16; o; o >>= 1) s += __shfl_xor_sync(0xFFFFFFFFu, s, o);
    __shared__ float red[8];
    if ((tid & 31) == 0) red[tid >> 5] = s;
    __syncthreads();
    if (tid == 0 || tid == 128) {
        int base = c * 4;
        float acc = red[base] + red[base + 1] + red[base + 2] + red[base + 3];
        out[144 + i * 2 + c] = acc + bg2[c];
    }
}

// ---------------- launch ----------------
extern "C" void kernel_launch(void* const* d_in, const int* in_sizes, int n_in,
                              void* d_out, int out_size)
{
    const float* x    = (const float*)d_in[0];
    const float* reh  = (const float*)d_in[1];
    const float* Wdr  = (const float*)d_in[2];
    const float* bdr  = (const float*)d_in[3];
    const float* Wv1  = (const float*)d_in[4];
    const float* bv1  = (const float*)d_in[5];
    const float* Wu1  = (const float*)d_in[6];
    const float* bu1  = (const float*)d_in[7];
    const float* Ww1  = (const float*)d_in[8];
    const float* bw1  = (const float*)d_in[9];
    const float* Wsc  = (const float*)d_in[10];
    const float* bsc  = (const float*)d_in[11];
    const float* Wv2  = (const float*)d_in[12];
    const float* bv2  = (const float*)d_in[13];
    const float* Wu2  = (const float*)d_in[14];
    const float* bu2  = (const float*)d_in[15];
    const float* Ww2  = (const float*)d_in[16];
    const float* bw2  = (const float*)d_in[17];
    const float* Wbc  = (const float*)d_in[18];
    const float* bbc  = (const float*)d_in[19];
    const float* Wf   = (const float*)d_in[20];
    const float* bf   = (const float*)d_in[21];
    const float* Wg1  = (const float*)d_in[22];
    const float* Wg1s = (const float*)d_in[23];
    const float* bg1  = (const float*)d_in[24];
    const float* Wg2  = (const float*)d_in[25];
    const float* Wg2s = (const float*)d_in[26];
    const float* bg2  = (const float*)d_in[27];
    float* out = (float*)d_out;

    cudaFuncSetAttribute(gemm_mma<0>, cudaFuncAttributeMaxDynamicSharedMemorySize, GEMM_SMEM);
    cudaFuncSetAttribute(gemm_mma<1>, cudaFuncAttributeMaxDynamicSharedMemorySize, GEMM_SMEM);
    cudaFuncSetAttribute(gemm_mma<2>, cudaFuncAttributeMaxDynamicSharedMemorySize, GEMM_SMEM);

    prepX<<<4096, 256>>>((const float4*)x);
    prepW<<<1792, 512>>>(Wdr, Wv1, Wu1, Wg1, Wg1s);
    gemm_mma<0><<<dim3(4, 1024), 256, GEMM_SMEM>>>(bdr, nullptr, nullptr);
    gemm_mma<1><<<dim3(2, 1024), 256, GEMM_SMEM>>>(bv1, bu1, Ww1);
    kCaf<<<dim3(8, 64), 256>>>(bw1);
    kSmall<<<1152, 256>>>(Wsc, bsc, out, Wv2, bv2, Wu2, bu2, Ww2, bw2, reh);
    kD2b<<<8, 512>>>(Wbc, bbc, out);
    gemmF2<<<17, 256>>>(Wf, bf);
    ksim<<<dim3(17, 17), 256>>>();
    ktop4<<<NN, 256>>>();
    kE5<<<NN, 256>>>();
    gemm_mma<2><<<dim3(4, 9), 256, GEMM_SMEM>>>(bg1, nullptr, nullptr);
    kE7<<<8, 256>>>(Wg2, Wg2s, bg2, out);
}

// round 17
// speedup vs baseline: 1.2325x; 1.2325x over previous
#include <cuda_runtime.h>
#include <cuda_fp16.h>
#include <math.h>
#include <limits.h>
#include <stdint.h>

#define B_    8
#define NINST 16384
#define D_    512
#define C_    2
#define G_    8
#define KNN   4
#define BUF_  1024
#define DA_   128
#define M_    (B_*NINST)     /* 131072 */
#define MG    2048
#define NG    64
#define NN    1032
#define NNP   1152           /* NN padded to 9*128 */

// ---------------- scratch (device globals; no allocation) ----------------
__device__ __half g_xh[(size_t)M_ * D_];
__device__ __half g_midh[(size_t)M_ * D_];
__device__ __half g_wh[D_ * D_];      // Wdr^T fp16  [n][k]
__device__ __half g_wvuh[256 * D_];   // packed [V|U] blocks fp16  [n][k]
__device__ __half g_wg1h[D_ * D_];    // Wg1^T fp16
__device__ __half g_wg1sh[D_ * D_];   // Wg1s^T fp16
__device__ __half g_hh[(size_t)NNP * D_];   // h fp16 (padded; rows >=NN stay zero)
__device__ __half g_m1h[(size_t)NNP * D_];  // m1 fp16 (padded; rows >=NN stay zero)
__device__ float g_apart[2 * M_];
__device__ float g_af[NG * D_];
__device__ float g_a2[NG];
__device__ float g_bag[B_ * D_];
__device__ float g_xc[NN * D_];
__device__ float g_x2[NN * 256];
__device__ float g_sim[NN * NN];
__device__ int   g_idx[NN * KNN];
__device__ float g_h[NN * D_];
__device__ float g_h1[NN * D_];

// ---------------- helpers ----------------
#define SWZ(o) ((o) ^ (((o) >> 3) & 0x70))

static __device__ __forceinline__ uint32_t smem_u32(const void* p) {
    uint32_t a;
    asm("{ .reg .u64 t; cvta.to.shared.u64 t, %1; cvt.u32.u64 %0, t; }" : "=r"(a) : "l"(p));
    return a;
}

#define CP_ASYNC16(dst, src) \
    asm volatile("cp.async.cg.shared.global [%0], [%1], 16;" :: "r"(dst), "l"(src))
#define CP_COMMIT asm volatile("cp.async.commit_group;" ::: "memory")
#define CP_WAIT2  asm volatile("cp.async.wait_group 2;" ::: "memory")
#define CP_WAIT1  asm volatile("cp.async.wait_group 1;" ::: "memory")
#define CP_WAIT0  asm volatile("cp.async.wait_group 0;" ::: "memory")

static __device__ __forceinline__ void ldsm4(uint32_t& r0, uint32_t& r1,
                                             uint32_t& r2, uint32_t& r3, uint32_t addr) {
    asm volatile("ldmatrix.sync.aligned.m8n8.x4.shared.b16 {%0,%1,%2,%3}, [%4];"
                 : "=r"(r0), "=r"(r1), "=r"(r2), "=r"(r3) : "r"(addr));
}
static __device__ __forceinline__ void mma16816(float* d, const uint32_t* a, const uint32_t* b) {
    asm volatile("mma.sync.aligned.m16n8k16.row.col.f32.f16.f16.f32 "
                 "{%0,%1,%2,%3}, {%4,%5,%6,%7}, {%8,%9}, {%0,%1,%2,%3};"
                 : "+f"(d[0]), "+f"(d[1]), "+f"(d[2]), "+f"(d[3])
                 : "r"(a[0]), "r"(a[1]), "r"(a[2]), "r"(a[3]), "r"(b[0]), "r"(b[1]));
}

static __device__ __forceinline__ uint32_t pack_h2(float a, float b) {
    __half h0 = __float2half_rn(a), h1 = __float2half_rn(b);
    return (uint32_t)__half_as_ushort(h0) | ((uint32_t)__half_as_ushort(h1) << 16);
}

// fast transcendentals: MUFU ex2 + rcp.approx
static __device__ __forceinline__ float ftanh(float x) {
    float xc = fminf(fmaxf(x, -15.f), 15.f);
    float t = __expf(2.f * xc);
    return __fdividef(t - 1.f, t + 1.f);
}
static __device__ __forceinline__ float fsigm(float x) {
    return __fdividef(1.f, 1.f + __expf(-x));
}

// ---------------- prep: x -> fp16, grid-stride ----------------
__global__ void prepX(const float4* __restrict__ x4)
{
    size_t idx = (size_t)blockIdx.x * 256 + threadIdx.x;
    const size_t stride = (size_t)4096 * 256;
#pragma unroll
    for (int s = 0; s < 16; s++) {
        size_t i = idx + (size_t)s * stride;
        float4 v = x4[i];
        uint2 hw;
        hw.x = pack_h2(v.x, v.y);
        hw.y = pack_h2(v.z, v.w);
        *(uint2*)(g_xh + i * 4) = hw;
    }
}

// ---------------- kTrans: coalesced smem-tiled fp32->fp16 transposes ----------------
// blocks 0..255: Wdr | 256..511: Wg1 | 512..767: Wg1s | 768..895: packed Wvu
__global__ void kTrans(const float* __restrict__ W,
                       const float* __restrict__ Wg1, const float* __restrict__ Wg1s,
                       const float* __restrict__ Wv, const float* __restrict__ Wu)
{
    __shared__ float tile[32][33];
    const int bx = blockIdx.x;
    const int tx = threadIdx.x & 31, ty = threadIdx.x >> 5;  // 32x8
    if (bx < 768) {
        const float* src = (bx < 256) ? W : (bx < 512 ? Wg1 : Wg1s);
        __half* dst = (bx < 256) ? g_wh : (bx < 512 ? g_wg1h : g_wg1sh);
        int t = bx & 255;
        int k0 = (t >> 4) * 32, n0 = (t & 15) * 32;
#pragma unroll
        for (int r = ty; r < 32; r += 8)
            tile[r][tx] = src[(size_t)(k0 + r) * 512 + n0 + tx];
        __syncthreads();
#pragma unroll
        for (int r = ty; r < 32; r += 8)
            dst[(size_t)(n0 + r) * 512 + k0 + tx] = __float2half_rn(tile[tx][r]);
    } else {
        // packed Wvu: out rows n (0..255), cols k (0..511)
        int t = bx - 768;                 // 128 tiles = 16 k-tiles x 8 n-tiles
        int k0 = (t >> 3) * 32;
        int n0 = (t & 7) * 32;
        int j0 = n0 & 127;
        int blk = n0 >> 7;
        const float* src = (j0 < 64) ? Wv : Wu;
        int gc0 = blk * 64 + (j0 & 63);
#pragma unroll
        for (int r = ty; r < 32; r += 8)
            tile[r][tx] = src[(size_t)(k0 + r) * 128 + gc0 + tx];
        __syncthreads();
#pragma unroll
        for (int r = ty; r < 32; r += 8)
            g_wvuh[(size_t)(n0 + r) * 512 + k0 + tx] = __float2half_rn(tile[tx][r]);
    }
}

// ---------------- mma.sync GEMM: 128x128 CTA tile, 3-stage ----------------
// MODE 0: kA — mid = relu(x@Wdr+b) -> g_midh (fp16);            K=512,   grid (4,1024)
// MODE 1: kB — fused gated-attention partial score -> g_apart;   K=512,   grid (2,1024)
// MODE 2: kG — h1 = relu(m1h@Wg1 + hh@Wg1s + bg1) -> g_h1 fp32; K=2*512, grid (4,9), M guarded
#define GEMM_SMEM 98816   /* 3 x 32KB stage buffers (+pad) */
template<int MODE>
__global__ void __launch_bounds__(256, 2) gemm_mma(const float* __restrict__ p0,
                                                   const float* __restrict__ p1,
                                                   const float* __restrict__ p2)
{
    extern __shared__ char smem[];
    const uint32_t sb = smem_u32(smem);
    const int tid = threadIdx.x;
    const int lane = tid & 31, warp = tid >> 5;
    const int wm = warp >> 1, wn = warp & 1;
    const int bm = blockIdx.y * 128;
    const int bn = blockIdx.x * 128;
    constexpr int NIT = (MODE == 2) ? 16 : 8;

    float d[2][8][4];
#pragma unroll
    for (int mi = 0; mi < 2; mi++)
#pragma unroll
        for (int n = 0; n < 8; n++)
#pragma unroll
            for (int j = 0; j < 4; j++) d[mi][n][j] = 0.f;

    auto issue = [&](int i) {
        const int seg = i >> 3, kc = i & 7, buf = i % 3;
        const __half* Aseg = (MODE == 0) ? g_xh
                           : (MODE == 1) ? g_midh
                           : (seg ? g_hh : g_m1h);
        const __half* Bseg = (MODE == 0) ? g_wh
                           : (MODE == 1) ? g_wvuh
                           : (seg ? g_wg1sh : g_wg1h);
        const uint32_t abase = sb + buf * 32768;
        const uint32_t bbase = abase + 16384;
        const int k0 = kc * 64;
#pragma unroll
        for (int p = 0; p < 4; p++) {
            int idx = tid + p * 256;
            int r = idx >> 3, c = idx & 7;
            CP_ASYNC16(abase + SWZ(r * 128 + c * 16),
                       Aseg + (size_t)(bm + r) * 512 + k0 + c * 8);
            CP_ASYNC16(bbase + SWZ(r * 128 + c * 16),
                       Bseg + (size_t)(bn + r) * 512 + k0 + c * 8);
        }
        CP_COMMIT;
    };

    issue(0); issue(1);
    for (int i = 0; i < NIT; i++) {
        if (i + 2 < NIT)      { issue(i + 2); CP_WAIT2; }
        else if (i + 1 < NIT) { CP_WAIT1; }
        else                  { CP_WAIT0; }
        __syncthreads();
        const uint32_t abase = sb + (i % 3) * 32768;
        const uint32_t bbase = abase + 16384;
        const int lr = lane & 7, quad = lane >> 3;
#pragma unroll
        for (int ks = 0; ks < 4; ks++) {
            const int k0 = ks * 16;
            uint32_t afr[2][4];
#pragma unroll
            for (int mi = 0; mi < 2; mi++) {
                int row = wm * 32 + mi * 16 + (quad & 1) * 8 + lr;
                int col = k0 + (quad >> 1) * 8;
                ldsm4(afr[mi][0], afr[mi][1], afr[mi][2], afr[mi][3],
                      abase + SWZ(row * 128 + col * 2));
            }
            uint32_t bfr[4][4];
#pragma unroll
            for (int nj = 0; nj < 4; nj++) {
                int row = wn * 64 + nj * 16 + (quad >> 1) * 8 + lr;
                int col = k0 + (quad & 1) * 8;
                ldsm4(bfr[nj][0], bfr[nj][1], bfr[nj][2], bfr[nj][3],
                      bbase + SWZ(row * 128 + col * 2));
            }
#pragma unroll
            for (int mi = 0; mi < 2; mi++)
#pragma unroll
                for (int n = 0; n < 8; n++)
                    mma16816(d[mi][n], afr[mi], &bfr[n >> 1][(n & 1) * 2]);
        }
        __syncthreads();
    }

    if (MODE == 1) {
        float* tile = (float*)smem;          // [128][132]
        float* sbv = (float*)(smem + 67584);
        float* sbu = sbv + 64;
        float* sww = sbu + 64;
        if (tid < 64) {
            int gc = blockIdx.x * 64 + tid;
            sbv[tid] = p0[gc]; sbu[tid] = p1[gc]; sww[tid] = p2[gc];
        }
#pragma unroll
        for (int mi = 0; mi < 2; mi++)
#pragma unroll
            for (int n = 0; n < 8; n++) {
                int r = wm * 32 + mi * 16 + (lane >> 2);
                int col = wn * 64 + n * 8 + (lane & 3) * 2;
                tile[r * 132 + col]           = d[mi][n][0];
                tile[r * 132 + col + 1]       = d[mi][n][1];
                tile[(r + 8) * 132 + col]     = d[mi][n][2];
                tile[(r + 8) * 132 + col + 1] = d[mi][n][3];
            }
        __syncthreads();
        int r = tid >> 1, half = tid & 1;
        float s = 0.f;
#pragma unroll
        for (int q = 0; q < 32; q++) {
            int j = half * 32 + q;
            float V = ftanh(tile[r * 132 + j] + sbv[j]);
            float U = fsigm(tile[r * 132 + 64 + j] + sbu[j]);
            s += V * U * sww[j];
        }
        s += __shfl_xor_sync(0xFFFFFFFFu, s, 1);
        if (half == 0) g_apart[(size_t)blockIdx.x * M_ + bm + r] = s;
        return;
    }

    // -------- MODE 0 / MODE 2 epilogue: bias + relu --------
    float* tile = (float*)smem;          // [128][136]
    float* sbias = (float*)(smem + 69632);
    if (tid < 128) sbias[tid] = p0[bn + tid];
#pragma unroll
    for (int mi = 0; mi < 2; mi++)
#pragma unroll
        for (int n = 0; n < 8; n++) {
            int r = wm * 32 + mi * 16 + (lane >> 2);
            int col = wn * 64 + n * 8 + (lane & 3) * 2;
            tile[r * 136 + col]           = d[mi][n][0];
            tile[r * 136 + col + 1]       = d[mi][n][1];
            tile[(r + 8) * 136 + col]     = d[mi][n][2];
            tile[(r + 8) * 136 + col + 1] = d[mi][n][3];
        }
    __syncthreads();
#pragma unroll
    for (int q = 0; q < 16; q++) {
        int idx = q * 256 + tid;
        int r = idx >> 5, c4 = (idx & 31) * 4;
        float4 v = *(const float4*)(tile + r * 136 + c4);
        v.x = fmaxf(v.x + sbias[c4 + 0], 0.f);
        v.y = fmaxf(v.y + sbias[c4 + 1], 0.f);
        v.z = fmaxf(v.z + sbias[c4 + 2], 0.f);
        v.w = fmaxf(v.w + sbias[c4 + 3], 0.f);
        if (MODE == 0) {
            uint2 hw;
            hw.x = pack_h2(v.x, v.y);
            hw.y = pack_h2(v.z, v.w);
            size_t off = (size_t)(bm + r) * 512 + bn + c4;
            *(uint2*)(g_midh + off) = hw;
        } else {
            int row = bm + r;
            if (row < NN)
                *(float4*)(g_h1 + (size_t)row * 512 + bn + c4) = v;
        }
    }
}

// ---------------- kCaf: inline softmax + af accumulation ----------------
__global__ __launch_bounds__(256) void kCaf(const float* __restrict__ bw)
{
    const int bg = blockIdx.y;
    const int cx = blockIdx.x;
    const int tid = threadIdx.x;
    const int lane = tid & 31, wi = tid >> 5;
    __shared__ float sw[MG];
    __shared__ float red[256];
    __shared__ float sred[8][64];
    const float bw0 = bw[0];

    float mx = -1e30f;
    for (int m = tid; m < MG; m += 256) {
        size_t row = (size_t)bg * MG + m;
        float a = g_apart[row] + g_apart[M_ + row] + bw0;
        sw[m] = a;
        mx = fmaxf(mx, a);
    }
    red[tid] = mx; __syncthreads();
    for (int s = 128; s > 0; s >>= 1) {
        if (tid < s) red[tid] = fmaxf(red[tid], red[tid + s]);
        __syncthreads();
    }
    mx = red[0]; __syncthreads();
    float sum = 0.f;
    for (int m = tid; m < MG; m += 256) {
        float e = __expf(sw[m] - mx);
        sw[m] = e; sum += e;
    }
    red[tid] = sum; __syncthreads();
    for (int s = 128; s > 0; s >>= 1) {
        if (tid < s) red[tid] += red[tid + s];
        __syncthreads();
    }
    const float inv = __fdividef(1.f, red[0]);
    __syncthreads();

    const int c0 = cx * 64 + lane * 2;
    const __half* mh = g_midh + (size_t)bg * MG * 512 + c0;
    float acc0 = 0.f, acc1 = 0.f;
    int mbase = wi * 256;
#pragma unroll 4
    for (int m = 0; m < 256; m++) {
        size_t off = (size_t)(mbase + m) * 512;
        __half2 hv = *(const __half2*)(mh + off);
        float wm = sw[mbase + m];
        acc0 += wm * __low2float(hv);
        acc1 += wm * __high2float(hv);
    }
    sred[wi][lane * 2] = acc0;
    sred[wi][lane * 2 + 1] = acc1;
    __syncthreads();
    if (tid < 64) {
        float s = 0.f;
#pragma unroll
        for (int w2 = 0; w2 < 8; w2++) s += sred[w2][tid];
        g_af[bg * 512 + cx * 64 + tid] = s * inv;
    }
}

// ---------------- dispatcher: kDsub (0-63) | kD1 (64-127) | copyReh (128-1151) ----------------
__global__ __launch_bounds__(256) void kSmall(
    const float* __restrict__ Wsc, const float* __restrict__ bsc, float* __restrict__ out,
    const float* __restrict__ Wv2, const float* __restrict__ bv2,
    const float* __restrict__ Wu2, const float* __restrict__ bu2,
    const float* __restrict__ Ww2, const float* __restrict__ bw2,
    const float* __restrict__ reh)
{
    __shared__ float sbuf[640];
    const int bx = blockIdx.x, tid = threadIdx.x;
    if (bx < 64) {
        int i = bx;
        int c = tid >> 7, dt = tid & 127;
        float s = 0.f;
        for (int d = dt; d < 512; d += 128) s += g_af[i * 512 + d] * Wsc[d * 2 + c];
#pragma unroll
        for (int o = 16; o; o >>= 1) s += __shfl_xor_sync(0xFFFFFFFFu, s, o);
        if ((tid & 31) == 0) sbuf[tid >> 5] = s;
        __syncthreads();
        if (tid == 0 || tid == 128) {
            int base = c * 4;
            float acc = sbuf[base] + sbuf[base + 1] + sbuf[base + 2] + sbuf[base + 3];
            int b = i >> 3, g = i & 7;
            out[16 + (g * 8 + b) * 2 + c] = acc + bsc[c];
        }
    } else if (bx < 128) {
        int i = bx - 64;
        float* s_af = sbuf;
        float* red  = sbuf + 512;
        for (int k = tid; k < 512; k += 256) s_af[k] = g_af[i * 512 + k];
        __syncthreads();
        int c = tid;
        if (c < 128) {
            float v = 0.f, u = 0.f;
            for (int k = 0; k < 512; k++) {
                float xv = s_af[k];
                v += xv * Wv2[k * 128 + c];
                u += xv * Wu2[k * 128 + c];
            }
            red[c] = ftanh(v + bv2[c]) * fsigm(u + bu2[c]) * Ww2[c];
        }
        __syncthreads();
        for (int s = 64; s > 0; s >>= 1) {
            if (c < s) red[c] += red[c + s];
            __syncthreads();
        }
        if (c == 0) g_a2[i] = red[0] + bw2[0];
    } else {
        int r = bx - 128;
        for (int d = tid; d < 512; d += 256)
            g_xc[(size_t)(8 + r) * 512 + d] = reh[(size_t)r * 512 + d];
    }
}

// ---------------- kD2b: bag_feat + x_concat rows 0..7 + bag_pred ----------------
__global__ void kD2b(const float* __restrict__ Wbc, const float* __restrict__ bbc,
                     float* __restrict__ out)
{
    int b = blockIdx.x;
    int t = threadIdx.x;
    __shared__ float w[8];
    __shared__ float red0[16], red1[16];
    if (t == 0) {
        float mx = -1e30f;
        for (int g = 0; g < 8; g++) mx = fmaxf(mx, g_a2[b * 8 + g]);
        float s = 0.f; float e[8];
        for (int g = 0; g < 8; g++) { e[g] = __expf(g_a2[b * 8 + g] - mx); s += e[g]; }
        float inv = __fdividef(1.f, s);
        for (int g = 0; g < 8; g++) w[g] = e[g] * inv;
    }
    __syncthreads();
    float acc = 0.f;
    for (int g = 0; g < 8; g++) acc += w[g] * g_af[(b * 8 + g) * 512 + t];
    g_bag[b * 512 + t] = acc;
    g_xc[b * 512 + t] = acc;
    float s0 = acc * Wbc[t * 2 + 0];
    float s1 = acc * Wbc[t * 2 + 1];
#pragma unroll
    for (int o = 16; o; o >>= 1) {
        s0 += __shfl_xor_sync(0xFFFFFFFFu, s0, o);
        s1 += __shfl_xor_sync(0xFFFFFFFFu, s1, o);
    }
    if ((t & 31) == 0) { red0[t >> 5] = s0; red1[t >> 5] = s1; }
    __syncthreads();
    if (t == 0) {
        float a0 = 0.f, a1 = 0.f;
#pragma unroll
        for (int q = 0; q < 16; q++) { a0 += red0[q]; a1 += red1[q]; }
        out[b * 2 + 0] = a0 + bbc[0];
        out[b * 2 + 1] = a1 + bbc[1];
    }
}

// ---------------- gemmF: g_x2 = leaky_relu(g_xc @ Wf + bf), M=1032 N=256 K=512
__global__ __launch_bounds__(256) void gemmF(const float* __restrict__ Bm,
                                             const float* __restrict__ bias)
{
    __shared__ float As[16][64];
    __shared__ float Bs[16][64];
    const int tid = threadIdx.x;
    const int bm = blockIdx.y * 64, bn = blockIdx.x * 64;
    const int lar = tid >> 2, lak = (tid & 3) * 4;
    const int lbr = tid >> 4, lbc = (tid & 15) * 4;
    const int tr = tid >> 4, tc = tid & 15;
    const int N = 256, K = 512;
    float acc[4][4];
#pragma unroll
    for (int i = 0; i < 4; i++)
#pragma unroll
        for (int j = 0; j < 4; j++) acc[i][j] = 0.f;

    for (int k0 = 0; k0 < K; k0 += 16) {
        float4 av = make_float4(0.f, 0.f, 0.f, 0.f);
        if (bm + lar < NN) av = *(const float4*)(g_xc + (size_t)(bm + lar) * K + k0 + lak);
        As[lak + 0][lar] = av.x; As[lak + 1][lar] = av.y;
        As[lak + 2][lar] = av.z; As[lak + 3][lar] = av.w;
        *(float4*)&Bs[lbr][lbc] = *(const float4*)(Bm + (size_t)(k0 + lbr) * N + bn + lbc);
        __syncthreads();
#pragma unroll
        for (int k = 0; k < 16; k++) {
            float4 a = *(const float4*)&As[k][tr * 4];
            float4 b = *(const float4*)&Bs[k][tc * 4];
            float ar[4] = {a.x, a.y, a.z, a.w};
            float br[4] = {b.x, b.y, b.z, b.w};
#pragma unroll
            for (int i = 0; i < 4; i++)
#pragma unroll
                for (int j = 0; j < 4; j++) acc[i][j] += ar[i] * br[j];
        }
        __syncthreads();
    }
#pragma unroll
    for (int i = 0; i < 4; i++) {
        int row = bm + tr * 4 + i;
#pragma unroll
        for (int j = 0; j < 4; j++) {
            int col = bn + tc * 4 + j;
            if (row < NN) {
                float v = acc[i][j] + bias[col];
                v = (v >= 0.f) ? v : 0.01f * v;
                g_x2[(size_t)row * N + col] = v;
            }
        }
    }
}

// ---------------- row-normalize _x (256 cols)
__global__ void knorm()
{
    int r = blockIdx.x, tid = threadIdx.x;
    float v = g_x2[(size_t)r * 256 + tid];
    __shared__ float red[256];
    red[tid] = v * v; __syncthreads();
    for (int s = 128; s > 0; s >>= 1) {
        if (tid < s) red[tid] += red[tid + s];
        __syncthreads();
    }
    float nrm = sqrtf(red[0]) + 1e-12f;
    g_x2[(size_t)r * 256 + tid] = v / nrm;
}

// ---------------- sim = xn @ xn^T (NT), guarded 64x64
__global__ __launch_bounds__(256) void ksim()
{
    __shared__ float As[16][64];
    __shared__ float Bs[16][64];
    const int tid = threadIdx.x;
    const int bm = blockIdx.y * 64, bn = blockIdx.x * 64;
    const int lar = tid >> 2, lak = (tid & 3) * 4;
    const int tr = tid >> 4, tc = tid & 15;
    float acc[4][4];
#pragma unroll
    for (int i = 0; i < 4; i++)
#pragma unroll
        for (int j = 0; j < 4; j++) acc[i][j] = 0.f;

    for (int k0 = 0; k0 < 256; k0 += 16) {
        float4 av = make_float4(0.f, 0.f, 0.f, 0.f);
        float4 bv = make_float4(0.f, 0.f, 0.f, 0.f);
        if (bm + lar < NN) av = *(const float4*)(g_x2 + (size_t)(bm + lar) * 256 + k0 + lak);
        if (bn + lar < NN) bv = *(const float4*)(g_x2 + (size_t)(bn + lar) * 256 + k0 + lak);
        As[lak + 0][lar] = av.x; As[lak + 1][lar] = av.y;
        As[lak + 2][lar] = av.z; As[lak + 3][lar] = av.w;
        Bs[lak + 0][lar] = bv.x; Bs[lak + 1][lar] = bv.y;
        Bs[lak + 2][lar] = bv.z; Bs[lak + 3][lar] = bv.w;
        __syncthreads();
#pragma unroll
        for (int k = 0; k < 16; k++) {
            float4 a = *(const float4*)&As[k][tr * 4];
            float4 b = *(const float4*)&Bs[k][tc * 4];
            float ar[4] = {a.x, a.y, a.z, a.w};
            float br[4] = {b.x, b.y, b.z, b.w};
#pragma unroll
            for (int i = 0; i < 4; i++)
#pragma unroll
                for (int j = 0; j < 4; j++) acc[i][j] += ar[i] * br[j];
        }
        __syncthreads();
    }
#pragma unroll
    for (int i = 0; i < 4; i++) {
        int row = bm + tr * 4 + i;
#pragma unroll
        for (int j = 0; j < 4; j++) {
            int col = bn + tc * 4 + j;
            if (row < NN && col < NN)
                g_sim[(size_t)row * NN + col] = acc[i][j];
        }
    }
}

// ---------------- top-4 (jax tie-break) fused with h = pad + mean(xc[idx]) ----------------
__device__ __forceinline__ void top4_insert(float* v, int* ix, float val, int id)
{
    for (int k = 0; k < 4; k++) {
        if (val > v[k] || (val == v[k] && id < ix[k])) {
            for (int q = 3; q > k; q--) { v[q] = v[q - 1]; ix[q] = ix[q - 1]; }
            v[k] = val; ix[k] = id;
            return;
        }
    }
}

__global__ void ktop4()
{
    int row = blockIdx.x, tid = threadIdx.x;
    const float* s = g_sim + (size_t)row * NN;
    float v[4] = {-1e30f, -1e30f, -1e30f, -1e30f};
    int ix[4] = {INT_MAX, INT_MAX, INT_MAX, INT_MAX};
    for (int c = tid; c < NN; c += 256) top4_insert(v, ix, s[c], c);
    __shared__ float sv[256][4];
    __shared__ int si[256][4];
#pragma unroll
    for (int k = 0; k < 4; k++) { sv[tid][k] = v[k]; si[tid][k] = ix[k]; }
    __syncthreads();
    for (int stride = 128; stride > 0; stride >>= 1) {
        if (tid < stride) {
#pragma unroll
            for (int k = 0; k < 4; k++)
                top4_insert(sv[tid], si[tid], sv[tid + stride][k], si[tid + stride][k]);
        }
        __syncthreads();
    }
    if (tid < 4) g_idx[row * 4 + tid] = si[0][tid];
    __syncthreads();
    int i0 = si[0][0], i1 = si[0][1], i2 = si[0][2], i3 = si[0][3];
    for (int d = tid; d < 512; d += 256) {
        float e = 0.25f * (g_xc[(size_t)i0 * 512 + d] + g_xc[(size_t)i1 * 512 + d] +
                           g_xc[(size_t)i2 * 512 + d] + g_xc[(size_t)i3 * 512 + d]);
        float p = (row < 8) ? g_bag[row * 512 + d] : 0.f;
        float hv = p + e;
        g_h[(size_t)row * 512 + d] = hv;
        g_hh[(size_t)row * 512 + d] = __float2half_rn(hv);
    }
}

// ---------------- kE5: m1h = fp16(mean(h[idx])) ----------------
__global__ void kE5()
{
    int i = blockIdx.x, tid = threadIdx.x;
    int i0 = g_idx[i * 4 + 0], i1 = g_idx[i * 4 + 1];
    int i2 = g_idx[i * 4 + 2], i3 = g_idx[i * 4 + 3];
    for (int d = tid; d < 512; d += 256) {
        float m1 = 0.25f *
            (g_h[(size_t)i0 * 512 + d] + g_h[(size_t)i1 * 512 + d] +
             g_h[(size_t)i2 * 512 + d] + g_h[(size_t)i3 * 512 + d]);
        g_m1h[(size_t)i * 512 + d] = __float2half_rn(m1);
    }
}

// ---------------- logits rows 0..7 -> out[144..159]; grid 8, block 256
__global__ void kE7(const float* __restrict__ Wg2, const float* __restrict__ Wg2s,
                    const float* __restrict__ bg2, float* __restrict__ out)
{
    int i = blockIdx.x, tid = threadIdx.x;
    int c = tid >> 7, dt = tid & 127;
    int i0 = g_idx[i * 4 + 0], i1 = g_idx[i * 4 + 1];
    int i2 = g_idx[i * 4 + 2], i3 = g_idx[i * 4 + 3];
    float s = 0.f;
    for (int d = dt; d < 512; d += 128) {
        float m2 = 0.25f * (g_h1[(size_t)i0 * 512 + d] + g_h1[(size_t)i1 * 512 + d] +
                            g_h1[(size_t)i2 * 512 + d] + g_h1[(size_t)i3 * 512 + d]);
        s += m2 * Wg2[d * 2 + c] + g_h1[(size_t)i * 512 + d] * Wg2s[d * 2 + c];
    }
#pragma unroll
    for (int o = 16; o; o >>= 1) s += __shfl_xor_sync(0xFFFFFFFFu, s, o);
    __shared__ float red[8];
    if ((tid & 31) == 0) red[tid >> 5] = s;
    __syncthreads();
    if (tid == 0 || tid == 128) {
        int base = c * 4;
        float acc = red[base] + red[base + 1] + red[base + 2] + red[base + 3];
        out[144 + i * 2 + c] = acc + bg2[c];
    }
}

// ---------------- launch ----------------
extern "C" void kernel_launch(void* const* d_in, const int* in_sizes, int n_in,
                              void* d_out, int out_size)
{
    const float* x    = (const float*)d_in[0];
    const float* reh  = (const float*)d_in[1];
    const float* Wdr  = (const float*)d_in[2];
    const float* bdr  = (const float*)d_in[3];
    const float* Wv1  = (const float*)d_in[4];
    const float* bv1  = (const float*)d_in[5];
    const float* Wu1  = (const float*)d_in[6];
    const float* bu1  = (const float*)d_in[7];
    const float* Ww1  = (const float*)d_in[8];
    const float* bw1  = (const float*)d_in[9];
    const float* Wsc  = (const float*)d_in[10];
    const float* bsc  = (const float*)d_in[11];
    const float* Wv2  = (const float*)d_in[12];
    const float* bv2  = (const float*)d_in[13];
    const float* Wu2  = (const float*)d_in[14];
    const float* bu2  = (const float*)d_in[15];
    const float* Ww2  = (const float*)d_in[16];
    const float* bw2  = (const float*)d_in[17];
    const float* Wbc  = (const float*)d_in[18];
    const float* bbc  = (const float*)d_in[19];
    const float* Wf   = (const float*)d_in[20];
    const float* bf   = (const float*)d_in[21];
    const float* Wg1  = (const float*)d_in[22];
    const float* Wg1s = (const float*)d_in[23];
    const float* bg1  = (const float*)d_in[24];
    const float* Wg2  = (const float*)d_in[25];
    const float* Wg2s = (const float*)d_in[26];
    const float* bg2  = (const float*)d_in[27];
    float* out = (float*)d_out;

    cudaFuncSetAttribute(gemm_mma<0>, cudaFuncAttributeMaxDynamicSharedMemorySize, GEMM_SMEM);
    cudaFuncSetAttribute(gemm_mma<1>, cudaFuncAttributeMaxDynamicSharedMemorySize, GEMM_SMEM);
    cudaFuncSetAttribute(gemm_mma<2>, cudaFuncAttributeMaxDynamicSharedMemorySize, GEMM_SMEM);

    prepX<<<4096, 256>>>((const float4*)x);
    kTrans<<<896, 256>>>(Wdr, Wg1, Wg1s, Wv1, Wu1);
    gemm_mma<0><<<dim3(4, 1024), 256, GEMM_SMEM>>>(bdr, nullptr, nullptr);
    gemm_mma<1><<<dim3(2, 1024), 256, GEMM_SMEM>>>(bv1, bu1, Ww1);
    kCaf<<<dim3(8, 64), 256>>>(bw1);
    kSmall<<<1152, 256>>>(Wsc, bsc, out, Wv2, bv2, Wu2, bu2, Ww2, bw2, reh);
    kD2b<<<8, 512>>>(Wbc, bbc, out);
    gemmF<<<dim3(4, 17), 256>>>(Wf, bf);
    knorm<<<NN, 256>>>();
    ksim<<<dim3(17, 17), 256>>>();
    ktop4<<<NN, 256>>>();
    kE5<<<NN, 256>>>();
    gemm_mma<2><<<dim3(4, 9), 256, GEMM_SMEM>>>(bg1, nullptr, nullptr);
    kE7<<<8, 256>>>(Wg2, Wg2s, bg2, out);
}